// round 8
// baseline (speedup 1.0000x reference)
#include <cuda_runtime.h>
#include <cuda_bf16.h>
#include <cstdint>

#define NUM_CH   544     // 32 batches * 17 keypoints
#define HH       256
#define WW       256
#define MAXP     30
#define STRIDE_  4
#define THRESH   0.1f
#define CUT      0.9985f // ~98 threshold-only candidates/channel expected
#define CAP      512
#define FULL     0xffffffffu

// Streaming kernel geometry: 544*65536/4 float4s, 16 per thread, exact cover.
#define TOT4     (NUM_CH * 16384)          // 8,912,896 float4
#define T1       256
#define NB1      2176                      // NB1*T1*16 == TOT4
#define NTHR     (NB1 * T1)                // 557,056

#define RPW      16
#define T2       512

// Per-channel candidate lists (gmem). g_cnt is zero-initialized at load and
// re-zeroed by select_kernel at the end of every call -> deterministic state.
__device__ int   g_cnt[NUM_CH];
__device__ float g_cs [NUM_CH * CAP];
__device__ int   g_ci [NUM_CH * CAP];

// Fallback scratch (exact path, never triggered on this input).
__device__ float g_fb_score[(size_t)NUM_CH * 65536];
__device__ int   g_fb_idx  [(size_t)NUM_CH * 65536];

// ---------------- Kernel 1: pure streaming threshold scan -------------------
__global__ __launch_bounds__(T1, 6)
void scan_kernel(const float4* __restrict__ hm4)
{
    const int t = blockIdx.x * T1 + threadIdx.x;

    #pragma unroll
    for (int b = 0; b < 2; ++b) {
        float4 v[8];
        // 8 independent, fully-coalesced LDG.128 front-batched for MLP
        #pragma unroll
        for (int i = 0; i < 8; ++i)
            v[i] = hm4[t + (size_t)(b * 8 + i) * NTHR];

        #pragma unroll
        for (int i = 0; i < 8; ++i) {
            const float mx = fmaxf(fmaxf(v[i].x, v[i].y), fmaxf(v[i].z, v[i].w));
            if (mx > CUT) {                       // ~0.6% of float4s
                const int q  = t + (b * 8 + i) * NTHR;
                const int ch = q >> 14;           // 16384 float4 per channel
                const int fb = (q & 16383) * 4;   // flat pixel idx in channel
                float* cs = g_cs + ch * CAP;
                int*   ci = g_ci + ch * CAP;
                if (v[i].x > CUT) { int p = atomicAdd(&g_cnt[ch], 1); if (p < CAP) { cs[p] = v[i].x; ci[p] = fb;     } }
                if (v[i].y > CUT) { int p = atomicAdd(&g_cnt[ch], 1); if (p < CAP) { cs[p] = v[i].y; ci[p] = fb + 1; } }
                if (v[i].z > CUT) { int p = atomicAdd(&g_cnt[ch], 1); if (p < CAP) { cs[p] = v[i].z; ci[p] = fb + 2; } }
                if (v[i].w > CUT) { int p = atomicAdd(&g_cnt[ch], 1); if (p < CAP) { cs[p] = v[i].w; ci[p] = fb + 3; } }
            }
        }
    }
}

// ---------------- Fallback: full NMS scan (proven, exact) -------------------
static __device__ __noinline__ void scan_pass(const float* __restrict__ chm,
                                              float cut, float* ds, int* di,
                                              int cap, int* cnt)
{
    const int lane = threadIdx.x & 31;
    const int wid  = threadIdx.x >> 5;
    const int r0   = wid * RPW;
    const int c0   = lane * 8;
    const float NI = __int_as_float(0xff800000);

    float P0[8], P1[8], P2[8], vD[8], rmA[8], rmB[8];

    auto LD = [&](int row, float* dst) {
        if ((unsigned)row < HH) {
            const float4 lo = *(const float4*)(chm + row * WW + c0);
            const float4 hi = *(const float4*)(chm + row * WW + c0 + 4);
            dst[0]=lo.x; dst[1]=lo.y; dst[2]=lo.z; dst[3]=lo.w;
            dst[4]=hi.x; dst[5]=hi.y; dst[6]=hi.z; dst[7]=hi.w;
        } else {
            for (int i = 0; i < 8; ++i) dst[i] = NI;
        }
    };

    LD(r0 - 1, P0);
    LD(r0,     P1);
    for (int i = 0; i < 8; ++i) { rmA[i] = NI; rmB[i] = NI; vD[i] = NI; }

    for (int t = 0; t < RPW + 2; ++t) {
        const int rr = r0 - 1 + t;
        if (t <= RPW - 1) {
            LD(rr + 2, P2);
        } else {
            for (int i = 0; i < 8; ++i) P2[i] = NI;
        }
        float lft = __shfl_up_sync(FULL, P0[7], 1);
        if (lane == 0)  lft = NI;
        float rgt = __shfl_down_sync(FULL, P0[0], 1);
        if (lane == 31) rgt = NI;

        float m[7];
        for (int i = 0; i < 7; ++i) m[i] = fmaxf(P0[i], P0[i + 1]);
        float rmC[8];
        rmC[0] = fmaxf(lft, m[0]);
        for (int i = 1; i < 7; ++i) rmC[i] = fmaxf(m[i - 1], P0[i + 1]);
        rmC[7] = fmaxf(m[6], rgt);

        if (t >= 2) {
            const int dr = rr - 1;
            for (int i = 0; i < 8; ++i) {
                const float w = fmaxf(fmaxf(rmA[i], rmB[i]), rmC[i]);
                if (vD[i] > cut && vD[i] == w) {
                    const int p = atomicAdd(cnt, 1);
                    if (p < cap) { ds[p] = vD[i]; di[p] = dr * WW + c0 + i; }
                }
            }
        }
        for (int i = 0; i < 8; ++i) {
            rmA[i] = rmB[i]; rmB[i] = rmC[i];
            vD[i]  = P0[i];  P0[i]  = P1[i]; P1[i] = P2[i];
        }
    }
}

// ---------------- Kernel 2: window check + rank + output --------------------
struct Sm {
    float ps[CAP]; int pi[CAP];
    int pcount;
    int fcount;
};

__global__ __launch_bounds__(T2, 2)
void select_kernel(const float* __restrict__ hm, float* __restrict__ out)
{
    __shared__ Sm s;
    const int tid = threadIdx.x;
    const int ch  = blockIdx.x;
    const float* __restrict__ chm = hm + (size_t)ch * HH * WW;
    const float NI = __int_as_float(0xff800000);

    if (tid == 0) { s.pcount = 0; s.fcount = 0; }
    __syncthreads();

    const int cnt = g_cnt[ch];
    const bool ok = (cnt <= CAP);
    const int nc  = min(cnt, CAP);

    // 3x3 window check on the ~98 candidates (scattered gmem reads)
    if (ok) {
        const float* cs = g_cs + ch * CAP;
        const int*   ci = g_ci + ch * CAP;
        for (int i = tid; i < nc; i += T2) {
            const float v  = cs[i];
            const int   id = ci[i];
            const int x = id & (WW - 1);
            const int y = id >> 8;
            const float* rp = chm + id;
            bool peak = true;
            if (x > 0      && __ldg(rp - 1)        > v) peak = false;
            if (x < WW - 1 && __ldg(rp + 1)        > v) peak = false;
            if (y > 0) {
                if (              __ldg(rp - WW)     > v) peak = false;
                if (x > 0      && __ldg(rp - WW - 1) > v) peak = false;
                if (x < WW - 1 && __ldg(rp - WW + 1) > v) peak = false;
            }
            if (y < HH - 1) {
                if (              __ldg(rp + WW)     > v) peak = false;
                if (x > 0      && __ldg(rp + WW - 1) > v) peak = false;
                if (x < WW - 1 && __ldg(rp + WW + 1) > v) peak = false;
            }
            if (peak) {
                const int p = atomicAdd(&s.pcount, 1);   // p < nc <= CAP
                s.ps[p] = v; s.pi[p] = id;
            }
        }
    }
    __syncthreads();

    int n = ok ? s.pcount : 0;
    const float* rs = s.ps;
    const int*   ri = s.pi;

    if (!ok || n < MAXP) {
        // Exact fallback: full NMS scan at THRESH into global scratch.
        float* gs = g_fb_score + (size_t)ch * 65536;
        int*   gi = g_fb_idx   + (size_t)ch * 65536;
        scan_pass(chm, THRESH, gs, gi, 65536, &s.fcount);
        __syncthreads();
        n = min(s.fcount, 65536);
        rs = gs; ri = gi;
    }

    // Exact rank (score desc, idx asc tiebreak == lax.top_k order).
    for (int i = tid; i < n; i += T2) {
        const float sc = rs[i];
        const int   id = ri[i];
        int rank = 0;
        for (int j = 0; j < n; ++j) {
            const float sj = rs[j];
            rank += (sj > sc) || (sj == sc && ri[j] < id);
        }
        if (rank < MAXP) {
            const int x  = id & (WW - 1);
            const int y  = id >> 8;
            const int ob = ch * MAXP + rank;
            out[ob * 2]                 = (float)(x * STRIDE_);
            out[ob * 2 + 1]             = (float)(y * STRIDE_);
            out[NUM_CH * MAXP * 2 + ob] = sc;     // scores segment
            out[NUM_CH * MAXP * 3 + ob] = 1.0f;   // valid segment
        }
    }
    // Padding (never needed on this input; keeps d_out fully written).
    for (int r = n + tid; r < MAXP; r += T2) {
        const int ob = ch * MAXP + r;
        out[ob * 2]                 = 0.0f;
        out[ob * 2 + 1]             = 0.0f;
        out[NUM_CH * MAXP * 2 + ob] = NI;
        out[NUM_CH * MAXP * 3 + ob] = 0.0f;
    }

    // Reset per-channel counter so the next call (graph replay) sees zeros.
    __syncthreads();
    if (tid == 0) g_cnt[ch] = 0;
}

extern "C" void kernel_launch(void* const* d_in, const int* in_sizes, int n_in,
                              void* d_out, int out_size)
{
    const float* hm = (const float*)d_in[0];
    float* out = (float*)d_out;
    scan_kernel<<<NB1, T1>>>((const float4*)hm);
    select_kernel<<<NUM_CH, T2>>>(hm, out);
}

// round 10
// speedup vs baseline: 1.2061x; 1.2061x over previous
#include <cuda_runtime.h>
#include <cuda_bf16.h>
#include <cstdint>

#define NUM_CH   544     // 32 batches * 17 keypoints
#define HH       256
#define WW       256
#define MAXP     30
#define STRIDE_  4
#define THRESH   0.1f
#define CUT      0.9985f // ~98 threshold-only candidates/channel expected
#define CAP      512
#define FULL     0xffffffffu

#define T1       256
#define QF4      4096              // float4 per quarter-channel (16384/4)
#define NBLK     (NUM_CH * 4)     // 2176 blocks, one per quarter-channel

// Per-channel state (zero-initialized at module load; the selecting block
// resets both counters at the end of each call -> deterministic for replay).
__device__ int   g_cnt [NUM_CH];
__device__ int   g_done[NUM_CH];
__device__ float g_cs  [NUM_CH * CAP];
__device__ int   g_ci  [NUM_CH * CAP];

// Fallback scratch (exact path, never triggered on this input).
__device__ float g_fb_score[(size_t)NUM_CH * 65536];
__device__ int   g_fb_idx  [(size_t)NUM_CH * 65536];

// ---------------- Fallback: full NMS scan (exact; 8 warps x 32 rows) --------
static __device__ __noinline__ void scan_pass(const float* __restrict__ chm,
                                              float cut, float* ds, int* di,
                                              int cap, int* cnt)
{
    const int lane = threadIdx.x & 31;
    const int wid  = threadIdx.x >> 5;   // 0..7
    const int r0   = wid * 32;
    const int c0   = lane * 8;
    const float NI = __int_as_float(0xff800000);

    float P0[8], P1[8], P2[8], vD[8], rmA[8], rmB[8];

    auto LD = [&](int row, float* dst) {
        if ((unsigned)row < HH) {
            const float4 lo = *(const float4*)(chm + row * WW + c0);
            const float4 hi = *(const float4*)(chm + row * WW + c0 + 4);
            dst[0]=lo.x; dst[1]=lo.y; dst[2]=lo.z; dst[3]=lo.w;
            dst[4]=hi.x; dst[5]=hi.y; dst[6]=hi.z; dst[7]=hi.w;
        } else {
            for (int i = 0; i < 8; ++i) dst[i] = NI;
        }
    };

    LD(r0 - 1, P0);
    LD(r0,     P1);
    for (int i = 0; i < 8; ++i) { rmA[i] = NI; rmB[i] = NI; vD[i] = NI; }

    for (int t = 0; t < 32 + 2; ++t) {
        const int rr = r0 - 1 + t;
        if (t <= 31) {
            LD(rr + 2, P2);
        } else {
            for (int i = 0; i < 8; ++i) P2[i] = NI;
        }
        float lft = __shfl_up_sync(FULL, P0[7], 1);
        if (lane == 0)  lft = NI;
        float rgt = __shfl_down_sync(FULL, P0[0], 1);
        if (lane == 31) rgt = NI;

        float m[7];
        for (int i = 0; i < 7; ++i) m[i] = fmaxf(P0[i], P0[i + 1]);
        float rmC[8];
        rmC[0] = fmaxf(lft, m[0]);
        for (int i = 1; i < 7; ++i) rmC[i] = fmaxf(m[i - 1], P0[i + 1]);
        rmC[7] = fmaxf(m[6], rgt);

        if (t >= 2) {
            const int dr = rr - 1;
            for (int i = 0; i < 8; ++i) {
                const float w = fmaxf(fmaxf(rmA[i], rmB[i]), rmC[i]);
                if (vD[i] > cut && vD[i] == w) {
                    const int p = atomicAdd(cnt, 1);
                    if (p < cap) { ds[p] = vD[i]; di[p] = dr * WW + c0 + i; }
                }
            }
        }
        for (int i = 0; i < 8; ++i) {
            rmA[i] = rmB[i]; rmB[i] = rmC[i];
            vD[i]  = P0[i];  P0[i]  = P1[i]; P1[i] = P2[i];
        }
    }
}

// ---------------- Fused kernel: scan quarter + last-arriver selection -------
struct Sm {
    float ps[CAP]; int pi[CAP];
    int pcount;
    int fcount;
    int sel;
};

__global__ __launch_bounds__(T1, 4)
void pose_post_kernel(const float* __restrict__ hm, float* __restrict__ out)
{
    __shared__ Sm s;
    const int tid = threadIdx.x;
    const int ch  = blockIdx.x >> 2;
    const int qr  = blockIdx.x & 3;
    const float NI = __int_as_float(0xff800000);

    // ---- Phase A: stream this quarter-channel (16 coalesced float4/thread) --
    const float4* __restrict__ hm4 = (const float4*)hm;
    const int q0 = ch * 16384 + qr * QF4;

    #pragma unroll
    for (int g = 0; g < 2; ++g) {
        float4 v[8];
        #pragma unroll
        for (int i = 0; i < 8; ++i)
            v[i] = hm4[q0 + (g * 8 + i) * T1 + tid];

        #pragma unroll
        for (int i = 0; i < 8; ++i) {
            const float mx = fmaxf(fmaxf(v[i].x, v[i].y), fmaxf(v[i].z, v[i].w));
            if (mx > CUT) {                     // ~0.6% of float4s
                const int idx = q0 + (g * 8 + i) * T1 + tid;
                const int fb  = (idx & 16383) * 4;   // flat pixel idx in channel
                float* cs = g_cs + ch * CAP;
                int*   ci = g_ci + ch * CAP;
                if (v[i].x > CUT) { int p = atomicAdd(&g_cnt[ch], 1); if (p < CAP) { cs[p] = v[i].x; ci[p] = fb;     } }
                if (v[i].y > CUT) { int p = atomicAdd(&g_cnt[ch], 1); if (p < CAP) { cs[p] = v[i].y; ci[p] = fb + 1; } }
                if (v[i].z > CUT) { int p = atomicAdd(&g_cnt[ch], 1); if (p < CAP) { cs[p] = v[i].z; ci[p] = fb + 2; } }
                if (v[i].w > CUT) { int p = atomicAdd(&g_cnt[ch], 1); if (p < CAP) { cs[p] = v[i].w; ci[p] = fb + 3; } }
            }
        }
    }

    // ---- Release: EVERY thread fences its own appends, then block-sync, ----
    // ---- then one arrival atomic (threadFenceReduction pattern).        ----
    __threadfence();
    __syncthreads();
    if (tid == 0) {
        const int old = atomicAdd(&g_done[ch], 1);
        s.sel = (old == 3);
        s.pcount = 0; s.fcount = 0;
    }
    __syncthreads();
    if (!s.sel) return;
    __threadfence();                             // acquire others' appends

    const float* __restrict__ chm = hm + (size_t)ch * HH * WW;
    const int cnt = g_cnt[ch];
    const bool ok = (cnt <= CAP);
    const int nc  = min(cnt, CAP);

    // ---- Phase B: 3x3 window check (channel is L2-hot: just streamed) ------
    if (ok) {
        const float* cs = g_cs + ch * CAP;
        const int*   ci = g_ci + ch * CAP;
        for (int i = tid; i < nc; i += T1) {
            const float v  = cs[i];
            const int   id = ci[i];
            const int x = id & (WW - 1);
            const int y = id >> 8;
            const float* rp = chm + id;
            bool peak = true;
            if (x > 0      && __ldg(rp - 1)        > v) peak = false;
            if (x < WW - 1 && __ldg(rp + 1)        > v) peak = false;
            if (y > 0) {
                if (              __ldg(rp - WW)     > v) peak = false;
                if (x > 0      && __ldg(rp - WW - 1) > v) peak = false;
                if (x < WW - 1 && __ldg(rp - WW + 1) > v) peak = false;
            }
            if (y < HH - 1) {
                if (              __ldg(rp + WW)     > v) peak = false;
                if (x > 0      && __ldg(rp + WW - 1) > v) peak = false;
                if (x < WW - 1 && __ldg(rp + WW + 1) > v) peak = false;
            }
            if (peak) {
                const int p = atomicAdd(&s.pcount, 1);   // p < nc <= CAP
                s.ps[p] = v; s.pi[p] = id;
            }
        }
    }
    __syncthreads();

    int n = ok ? s.pcount : 0;
    const float* rs = s.ps;
    const int*   ri = s.pi;

    if (!ok || n < MAXP) {
        // Exact fallback: full NMS at THRESH into global scratch.
        float* gs = g_fb_score + (size_t)ch * 65536;
        int*   gi = g_fb_idx   + (size_t)ch * 65536;
        scan_pass(chm, THRESH, gs, gi, 65536, &s.fcount);
        __syncthreads();
        n = min(s.fcount, 65536);
        rs = gs; ri = gi;
    }

    // ---- Exact rank (score desc, idx asc tiebreak == lax.top_k order) ------
    for (int i = tid; i < n; i += T1) {
        const float sc = rs[i];
        const int   id = ri[i];
        int rank = 0;
        for (int j = 0; j < n; ++j) {
            const float sj = rs[j];
            rank += (sj > sc) || (sj == sc && ri[j] < id);
        }
        if (rank < MAXP) {
            const int x  = id & (WW - 1);
            const int y  = id >> 8;
            const int ob = ch * MAXP + rank;
            out[ob * 2]                 = (float)(x * STRIDE_);
            out[ob * 2 + 1]             = (float)(y * STRIDE_);
            out[NUM_CH * MAXP * 2 + ob] = sc;     // scores segment
            out[NUM_CH * MAXP * 3 + ob] = 1.0f;   // valid segment
        }
    }
    // Padding (never needed on this input; keeps d_out fully written).
    for (int r = n + tid; r < MAXP; r += T1) {
        const int ob = ch * MAXP + r;
        out[ob * 2]                 = 0.0f;
        out[ob * 2 + 1]             = 0.0f;
        out[NUM_CH * MAXP * 2 + ob] = NI;
        out[NUM_CH * MAXP * 3 + ob] = 0.0f;
    }

    // Reset per-channel state for the next call / graph replay.
    __syncthreads();
    if (tid == 0) { g_cnt[ch] = 0; g_done[ch] = 0; }
}

extern "C" void kernel_launch(void* const* d_in, const int* in_sizes, int n_in,
                              void* d_out, int out_size)
{
    const float* hm = (const float*)d_in[0];
    float* out = (float*)d_out;
    pose_post_kernel<<<NBLK, T1>>>(hm, out);
}